// round 13
// baseline (speedup 1.0000x reference)
#include <cuda_runtime.h>
#include <cstdint>

// hidden[1024], enc[65536,1024], W[1024,1024], b[1024]
// out[65536] = softmax(enc @ (W^T @ hidden) + b.hidden)
// b.hidden is a uniform shift across scores -> softmax-invariant -> dropped.

#define H 1024
#define S 65536
#define NSPLIT 64               // K1: 64 slabs x 16 rows
#define ROWS_PER_SLAB (H / NSPLIT)      // 16
#define ROWS_PER_BLK 64         // K2: rows per block
#define NBLK (S / ROWS_PER_BLK) // 1024
#define EXP_BLOCKS 64           // K3: 64 blocks * 256 thr * float4 = 65536

// ---- device scratch (no allocation allowed) ----
__device__ __align__(16) float g_vpart[NSPLIT * H];
__device__ __align__(16) float g_v[H];
__device__ unsigned g_maxu;
__device__ float g_psum[EXP_BLOCKS];
__device__ int g_c1 = 0;   // K1 arrival counter (reset by K2 for next replay)
__device__ int g_c3 = 0;   // K3 arrival counter (reset by K1 each replay)

// monotonic float<->uint encoding (order-preserving)
__device__ __forceinline__ unsigned enc_ord(float f) {
    unsigned u = __float_as_uint(f);
    return (u & 0x80000000u) ? ~u : (u | 0x80000000u);
}
__device__ __forceinline__ float dec_ord(unsigned u) {
    return (u & 0x80000000u) ? __uint_as_float(u ^ 0x80000000u)
                             : __uint_as_float(~u);
}

// ============ K1: v = W^T h, fused partial + reduce (grid-resident spin) ====
// grid 64 (single wave), block 256. Each block owns a 16-row slab; each
// thread owns one float4 column group (256 thr * 4 = all 1024 cols).
// Loads are explicitly batched 8-deep into registers BEFORE consumption so
// ptxas keeps 8 independent LDG.128 in flight per thread (fixes the
// regs=31 / 398GB/s serial-chain failure seen in R12 ncu).
__global__ __launch_bounds__(256) void v_kernel(
    const float* __restrict__ W, const float* __restrict__ h) {
    int tid = threadIdx.x;
    int i0 = blockIdx.x * ROWS_PER_SLAB;
    const float4* W4 = (const float4*)W;

    float hr[ROWS_PER_SLAB];
#pragma unroll
    for (int r = 0; r < ROWS_PER_SLAB; r++) hr[r] = __ldg(&h[i0 + r]);

    float4 a0 = make_float4(0.f, 0.f, 0.f, 0.f);
    float4 a1 = make_float4(0.f, 0.f, 0.f, 0.f);
    float4 w[8];
#pragma unroll
    for (int r = 0; r < 8; r++) w[r] = W4[(size_t)(i0 + r) * 256 + tid];
#pragma unroll
    for (int r = 0; r < 8; r++) {
        a0.x = fmaf(w[r].x, hr[r], a0.x);
        a0.y = fmaf(w[r].y, hr[r], a0.y);
        a0.z = fmaf(w[r].z, hr[r], a0.z);
        a0.w = fmaf(w[r].w, hr[r], a0.w);
    }
#pragma unroll
    for (int r = 0; r < 8; r++) w[r] = W4[(size_t)(i0 + 8 + r) * 256 + tid];
#pragma unroll
    for (int r = 0; r < 8; r++) {
        a1.x = fmaf(w[r].x, hr[8 + r], a1.x);
        a1.y = fmaf(w[r].y, hr[8 + r], a1.y);
        a1.z = fmaf(w[r].z, hr[8 + r], a1.z);
        a1.w = fmaf(w[r].w, hr[8 + r], a1.w);
    }
    float4 acc = make_float4(a0.x + a1.x, a0.y + a1.y, a0.z + a1.z, a0.w + a1.w);
    ((float4*)g_vpart)[blockIdx.x * 256 + tid] = acc;

    __syncthreads();
    if (tid == 0) {
        __threadfence();
        atomicAdd(&g_c1, 1);
    }
    if (blockIdx.x >= 4) return;

    // phase 2: blocks 0..3 reduce 64 partials per column (L2-resident)
    if (tid == 0) {
        while (*(volatile int*)&g_c1 < NSPLIT) __nanosleep(32);
        __threadfence();
    }
    __syncthreads();
    int col = blockIdx.x * 256 + tid;
    float s0 = 0.f, s1 = 0.f;
#pragma unroll
    for (int k = 0; k < NSPLIT; k += 2) {           // two chains: MLP + no
        s0 += g_vpart[k * H + col];                 // serial-add bottleneck
        s1 += g_vpart[(k + 1) * H + col];
    }
    g_v[col] = s0 + s1;
    if (col == 0) { g_maxu = 0u; g_c3 = 0; }  // resets for K2/K3 this replay
}

// ============ K2: scores = enc . v  + global max ============================
// grid NBLK, block 256: 8 warps x 8 rows; per-lane partials -> padded smem,
// deterministic serial reduce in phase 2 (no shuffles in the load loop).
// Even/odd k accumulators break the dependent-FMA chain between loads.
__global__ __launch_bounds__(256) void scores_kernel(
    const float* __restrict__ enc, float* __restrict__ out) {
    __shared__ __align__(16) float vs[H];
    __shared__ float part[ROWS_PER_BLK * 33];   // stride-33 pad: conflict-free
    __shared__ float wmax[2];

    int tid = threadIdx.x;
    ((float4*)vs)[tid] = ((const float4*)g_v)[tid];
    if (blockIdx.x == 0 && tid == 0) g_c1 = 0;  // reset for next replay's K1
    __syncthreads();

    int warp = tid >> 5, lane = tid & 31;
    int row0 = blockIdx.x * ROWS_PER_BLK + warp * 8;
    const float4* enc4 = (const float4*)enc;
    const float4* vs4 = (const float4*)vs;

#pragma unroll
    for (int r = 0; r < 8; r++) {
        const float4* p = enc4 + (size_t)(row0 + r) * (H / 4) + lane;
        float acc0 = 0.f, acc1 = 0.f;
#pragma unroll
        for (int k = 0; k < 8; k += 2) {
            float4 e0 = __ldcs(p + k * 32);      // streaming: no L2 pollute
            float4 e1 = __ldcs(p + (k + 1) * 32);
            float4 v0 = vs4[k * 32 + lane];
            float4 v1 = vs4[(k + 1) * 32 + lane];
            acc0 = fmaf(e0.x, v0.x, acc0);
            acc0 = fmaf(e0.y, v0.y, acc0);
            acc0 = fmaf(e0.z, v0.z, acc0);
            acc0 = fmaf(e0.w, v0.w, acc0);
            acc1 = fmaf(e1.x, v1.x, acc1);
            acc1 = fmaf(e1.y, v1.y, acc1);
            acc1 = fmaf(e1.z, v1.z, acc1);
            acc1 = fmaf(e1.w, v1.w, acc1);
        }
        part[(warp * 8 + r) * 33 + lane] = acc0 + acc1;  // no reduce in loop
    }
    __syncthreads();

    if (tid < ROWS_PER_BLK) {
        float s = 0.f;
#pragma unroll
        for (int k = 0; k < 32; k++) s += part[tid * 33 + k];  // deterministic
        out[blockIdx.x * ROWS_PER_BLK + tid] = s;              // coalesced
        float m = s;
#pragma unroll
        for (int o = 16; o > 0; o >>= 1)
            m = fmaxf(m, __shfl_xor_sync(0xffffffffu, m, o));
        if (lane == 0) wmax[tid >> 5] = m;
    }
    __syncthreads();
    if (tid == 0)
        atomicMax(&g_maxu, enc_ord(fmaxf(wmax[0], wmax[1])));  // order-invariant
}

// ============ K3: exp + global-sum + normalize, one kernel ==================
// grid 64 (single wave -> spin barrier safe), block 256, float4/thread.
// exp'd values stay in registers across the barrier: saves a 256KB re-read
// and an entire launch vs a split exp/normalize pair.
__global__ __launch_bounds__(256) void softmax_kernel(float* __restrict__ out) {
    __shared__ float wsum[8];
    __shared__ float sinv;
    int tid = threadIdx.x;
    int idx = blockIdx.x * 256 + tid;
    float gmax = dec_ord(g_maxu);

    float4 s = ((float4*)out)[idx];
    s.x = __expf(s.x - gmax);
    s.y = __expf(s.y - gmax);
    s.z = __expf(s.z - gmax);
    s.w = __expf(s.w - gmax);

    float l = (s.x + s.y) + (s.z + s.w);
#pragma unroll
    for (int o = 16; o > 0; o >>= 1)
        l += __shfl_xor_sync(0xffffffffu, l, o);
    if ((tid & 31) == 0) wsum[tid >> 5] = l;
    __syncthreads();

    if (tid == 0) {
        float b = 0.f;
#pragma unroll
        for (int w = 0; w < 8; w++) b += wsum[w];
        g_psum[blockIdx.x] = b;
        __threadfence();
        atomicAdd(&g_c3, 1);
        while (*(volatile int*)&g_c3 < EXP_BLOCKS) __nanosleep(32);
        __threadfence();
        float t = 0.f;
#pragma unroll
        for (int k = 0; k < EXP_BLOCKS; k++) t += g_psum[k];  // deterministic
        sinv = 1.0f / t;
    }
    __syncthreads();

    float inv = sinv;
    s.x *= inv; s.y *= inv; s.z *= inv; s.w *= inv;
    ((float4*)out)[idx] = s;
}

extern "C" void kernel_launch(void* const* d_in, const int* in_sizes, int n_in,
                              void* d_out, int out_size) {
    const float* hidden = (const float*)d_in[0];  // [1024]
    const float* enc    = (const float*)d_in[1];  // [65536,1024]
    const float* W      = (const float*)d_in[2];  // [1024,1024]
    // d_in[3] = b : unused (softmax shift-invariant)
    float* out = (float*)d_out;                   // [65536]

    v_kernel<<<NSPLIT, 256>>>(W, hidden);
    scores_kernel<<<NBLK, 256>>>(enc, out);
    softmax_kernel<<<EXP_BLOCKS, 256>>>(out);
}

// round 14
// speedup vs baseline: 1.1912x; 1.1912x over previous
#include <cuda_runtime.h>
#include <cstdint>

// hidden[1024], enc[65536,1024], W[1024,1024], b[1024]
// out[65536] = softmax(enc @ (W^T @ hidden) + b.hidden)
// b.hidden is a uniform shift across scores -> softmax-invariant -> dropped.

#define H 1024
#define S 65536
#define K1_SLABS 128            // K1a: 128 slabs x 8 rows
#define TILE_ROWS 64            // K2: rows per tile
#define NTILES (S / TILE_ROWS)  // 1024
#define K2_BLOCKS 148           // one persistent block per SM
#define K2_THREADS 1024         // 32 warps
#define EXP_BLOCKS 64           // K3: 64 blocks * 256 thr * float4 = 65536

// ---- device scratch (no allocation allowed) ----
__device__ __align__(16) float g_vpart[K1_SLABS * H];
__device__ __align__(16) float g_v[H];
__device__ unsigned g_maxu;
__device__ float g_psum[EXP_BLOCKS];
__device__ int g_tk = 0;   // K2 ticket counter (reset by K3 for next replay)
__device__ int g_c3 = 0;   // K3 arrival counter (reset by K1b each replay)

// monotonic float<->uint encoding (order-preserving)
__device__ __forceinline__ unsigned enc_ord(float f) {
    unsigned u = __float_as_uint(f);
    return (u & 0x80000000u) ? ~u : (u | 0x80000000u);
}
__device__ __forceinline__ float dec_ord(unsigned u) {
    return (u & 0x80000000u) ? __uint_as_float(u ^ 0x80000000u)
                             : __uint_as_float(~u);
}

// ============ K1a: slab partials of v = W^T h ===============================
// grid 128 (single wave), block 256. Block b covers rows [8b, 8b+8); thread
// owns one float4 column group. 8 independent LDG.128 per thread -> the whole
// 4 MB of W can be in flight across the grid. No spin, no reduce here.
__global__ __launch_bounds__(256) void v_part_kernel(
    const float* __restrict__ W, const float* __restrict__ h) {
    int tid = threadIdx.x;
    int i0 = blockIdx.x * 8;
    const float4* W4 = (const float4*)W;

    float hr[8];
#pragma unroll
    for (int r = 0; r < 8; r++) hr[r] = __ldg(&h[i0 + r]);
    float4 w[8];
#pragma unroll
    for (int r = 0; r < 8; r++) w[r] = W4[(size_t)(i0 + r) * 256 + tid];

    float4 a0 = make_float4(0.f, 0.f, 0.f, 0.f);
    float4 a1 = make_float4(0.f, 0.f, 0.f, 0.f);
#pragma unroll
    for (int r = 0; r < 8; r += 2) {
        a0.x = fmaf(w[r].x, hr[r], a0.x);
        a0.y = fmaf(w[r].y, hr[r], a0.y);
        a0.z = fmaf(w[r].z, hr[r], a0.z);
        a0.w = fmaf(w[r].w, hr[r], a0.w);
        a1.x = fmaf(w[r + 1].x, hr[r + 1], a1.x);
        a1.y = fmaf(w[r + 1].y, hr[r + 1], a1.y);
        a1.z = fmaf(w[r + 1].z, hr[r + 1], a1.z);
        a1.w = fmaf(w[r + 1].w, hr[r + 1], a1.w);
    }
    float4 acc = make_float4(a0.x + a1.x, a0.y + a1.y, a0.z + a1.z, a0.w + a1.w);
    ((float4*)g_vpart)[blockIdx.x * 256 + tid] = acc;
}

// ============ K1b: reduce 128 partials/col -> v; reset flags ================
// grid 32, block 256: 8 threads per column, 16 L2-resident partials each
// (independent addresses), then a fixed 8-way smem combine (deterministic).
__global__ __launch_bounds__(256) void v_reduce_kernel() {
    __shared__ float red[256];
    int tid = threadIdx.x;
    int col = blockIdx.x * 32 + (tid >> 3);
    int sub = tid & 7;

    float s0 = 0.f, s1 = 0.f;
#pragma unroll
    for (int i = 0; i < 16; i += 2) {
        s0 += g_vpart[(sub * 16 + i) * H + col];
        s1 += g_vpart[(sub * 16 + i + 1) * H + col];
    }
    red[tid] = s0 + s1;
    __syncthreads();
    if (sub == 0) {
        float s = 0.f;
#pragma unroll
        for (int k = 0; k < 8; k++) s += red[tid + k];   // fixed order
        g_v[col] = s;
    }
    if (blockIdx.x == 0 && tid == 0) { g_maxu = 0u; g_c3 = 0; }
}

// ============ K2: scores = enc . v, persistent + dynamic tickets ============
// grid 148 (1 block/SM, co-residency trivially guaranteed), block 1024
// (32 warps). Blocks pull 64-row tiles from an atomic ticket: order is
// non-deterministic but every tile's result and the max encoding are
// order-invariant -> deterministic output. Per tile: warp w handles rows
// {2w, 2w+1}; lane partials -> padded smem; 64 threads do a fixed serial
// reduce. v is staged in shared ONCE per block.
__global__ __launch_bounds__(K2_THREADS, 1) void scores_kernel(
    const float* __restrict__ enc, float* __restrict__ out) {
    __shared__ __align__(16) float vs[H];
    __shared__ float part[TILE_ROWS * 33];      // stride-33 pad: conflict-free
    __shared__ float wmax[2];
    __shared__ int s_t;

    int tid = threadIdx.x;
    if (tid < 256) ((float4*)vs)[tid] = ((const float4*)g_v)[tid];

    int warp = tid >> 5, lane = tid & 31;
    const float4* enc4 = (const float4*)enc;
    const float4* vs4 = (const float4*)vs;

    for (;;) {
        if (tid == 0) s_t = atomicAdd(&g_tk, 1);
        __syncthreads();                         // s_t valid; part[] reusable
        int t = s_t;
        if (t >= NTILES) break;
        int row0 = t * TILE_ROWS + warp * 2;

#pragma unroll
        for (int r = 0; r < 2; r++) {
            const float4* p = enc4 + (size_t)(row0 + r) * (H / 4) + lane;
            float acc0 = 0.f, acc1 = 0.f;
#pragma unroll
            for (int k = 0; k < 8; k += 2) {
                float4 e0 = __ldcs(p + k * 32);  // streaming: no L2 pollute
                float4 e1 = __ldcs(p + (k + 1) * 32);
                float4 v0 = vs4[k * 32 + lane];
                float4 v1 = vs4[(k + 1) * 32 + lane];
                acc0 = fmaf(e0.x, v0.x, acc0);
                acc0 = fmaf(e0.y, v0.y, acc0);
                acc0 = fmaf(e0.z, v0.z, acc0);
                acc0 = fmaf(e0.w, v0.w, acc0);
                acc1 = fmaf(e1.x, v1.x, acc1);
                acc1 = fmaf(e1.y, v1.y, acc1);
                acc1 = fmaf(e1.z, v1.z, acc1);
                acc1 = fmaf(e1.w, v1.w, acc1);
            }
            part[(warp * 2 + r) * 33 + lane] = acc0 + acc1;
        }
        __syncthreads();

        if (tid < TILE_ROWS) {
            float s = 0.f;
#pragma unroll
            for (int k = 0; k < 32; k++) s += part[tid * 33 + k];  // fixed order
            out[t * TILE_ROWS + tid] = s;                          // coalesced
            float m = s;
#pragma unroll
            for (int o = 16; o > 0; o >>= 1)
                m = fmaxf(m, __shfl_xor_sync(0xffffffffu, m, o));
            if (lane == 0) wmax[tid >> 5] = m;
        }
        __syncthreads();
        if (tid == 0)
            atomicMax(&g_maxu, enc_ord(fmaxf(wmax[0], wmax[1])));  // order-inv
    }
}

// ============ K3: exp + global-sum + normalize, one kernel ==================
// grid 64 (single wave -> spin barrier safe), block 256, float4/thread.
// exp'd values stay in registers across the barrier. Also resets the K2
// ticket counter for the next graph replay.
__global__ __launch_bounds__(256) void softmax_kernel(float* __restrict__ out) {
    __shared__ float wsum[8];
    __shared__ float sinv;
    int tid = threadIdx.x;
    int idx = blockIdx.x * 256 + tid;
    if (blockIdx.x == 0 && tid == 0) g_tk = 0;   // K2 done; safe to reset
    float gmax = dec_ord(g_maxu);

    float4 s = ((float4*)out)[idx];
    s.x = __expf(s.x - gmax);
    s.y = __expf(s.y - gmax);
    s.z = __expf(s.z - gmax);
    s.w = __expf(s.w - gmax);

    float l = (s.x + s.y) + (s.z + s.w);
#pragma unroll
    for (int o = 16; o > 0; o >>= 1)
        l += __shfl_xor_sync(0xffffffffu, l, o);
    if ((tid & 31) == 0) wsum[tid >> 5] = l;
    __syncthreads();

    if (tid == 0) {
        float b = 0.f;
#pragma unroll
        for (int w = 0; w < 8; w++) b += wsum[w];
        g_psum[blockIdx.x] = b;
        __threadfence();
        atomicAdd(&g_c3, 1);
        while (*(volatile int*)&g_c3 < EXP_BLOCKS) __nanosleep(32);
        __threadfence();
        float t = 0.f;
#pragma unroll
        for (int k = 0; k < EXP_BLOCKS; k++) t += g_psum[k];  // deterministic
        sinv = 1.0f / t;
    }
    __syncthreads();

    float inv = sinv;
    s.x *= inv; s.y *= inv; s.z *= inv; s.w *= inv;
    ((float4*)out)[idx] = s;
}

extern "C" void kernel_launch(void* const* d_in, const int* in_sizes, int n_in,
                              void* d_out, int out_size) {
    const float* hidden = (const float*)d_in[0];  // [1024]
    const float* enc    = (const float*)d_in[1];  // [65536,1024]
    const float* W      = (const float*)d_in[2];  // [1024,1024]
    // d_in[3] = b : unused (softmax shift-invariant)
    float* out = (float*)d_out;                   // [65536]

    v_part_kernel<<<K1_SLABS, 256>>>(W, hidden);
    v_reduce_kernel<<<H / 32, 256>>>();
    scores_kernel<<<K2_BLOCKS, K2_THREADS>>>(enc, out);
    softmax_kernel<<<EXP_BLOCKS, 256>>>(out);
}